// round 14
// baseline (speedup 1.0000x reference)
#include <cuda_runtime.h>
#include <cuda_fp16.h>
#include <math.h>
#include <stdint.h>

#define B_   4
#define T_   2048
#define D_   1024
#define NH_  8
#define H_   128
#define M_   (B_*T_)

// ---------------- scratch ----------------------------------------------------
__device__ __half g_qth[(size_t)M_*D_];    // q pre-rope fp16 [M,D]
__device__ __half g_kth[(size_t)M_*D_];    // k pre-rope fp16 [M,D]
__device__ __half g_qh[(size_t)M_*D_];     // [B,N,T,H] fp16 (pre-scaled by SC2)
__device__ __half g_kh[(size_t)M_*D_];     // [B,N,T,H] fp16
__device__ __half g_vh[(size_t)M_*D_];     // [B,N,H,T] fp16 (h-major)
__device__ __half g_xh[(size_t)M_*D_];     // x fp16
__device__ __half g_wh[(size_t)3*D_*D_];   // wq|wk|wv fp16

// ---------------- helpers ----------------------------------------------------
static __device__ __forceinline__ uint32_t smem_u32(const void* p) {
    uint32_t a;
    asm("{ .reg .u64 t; cvta.to.shared.u64 t, %1; cvt.u32.u64 %0, t; }"
        : "=r"(a) : "l"(p));
    return a;
}
static __device__ __forceinline__ void cp16(uint32_t dst, const void* src) {
    asm volatile("cp.async.cg.shared.global [%0], [%1], 16;" :: "r"(dst), "l"(src));
}
static __device__ __forceinline__ void cp_commit() {
    asm volatile("cp.async.commit_group;");
}
static __device__ __forceinline__ void cp_wait0() {
    asm volatile("cp.async.wait_group 0;" ::: "memory");
}
static __device__ __forceinline__ void cp_wait1() {
    asm volatile("cp.async.wait_group 1;" ::: "memory");
}
static __device__ __forceinline__ void mma_f16(float* d, const uint32_t* a,
                                               const uint32_t* b) {
    asm volatile(
        "mma.sync.aligned.m16n8k16.row.col.f32.f16.f16.f32 "
        "{%0,%1,%2,%3}, {%4,%5,%6,%7}, {%8,%9}, {%0,%1,%2,%3};"
        : "+f"(d[0]), "+f"(d[1]), "+f"(d[2]), "+f"(d[3])
        : "r"(a[0]), "r"(a[1]), "r"(a[2]), "r"(a[3]), "r"(b[0]), "r"(b[1]));
}
static __device__ __forceinline__ void ldm_x4(uint32_t* r, uint32_t addr) {
    asm volatile("ldmatrix.sync.aligned.m8n8.x4.shared.b16 {%0,%1,%2,%3}, [%4];"
        : "=r"(r[0]), "=r"(r[1]), "=r"(r[2]), "=r"(r[3]) : "r"(addr));
}
static __device__ __forceinline__ uint32_t pack_h2(float x, float y) {
    __half2 h = __floats2half2_rn(x, y);
    uint32_t u;
    memcpy(&u, &h, 4);
    return u;
}
static __device__ __forceinline__ float ex2(float x) {
    float r;
    asm("ex2.approx.f32 %0, %1;" : "=f"(r) : "f"(x));
    return r;
}

// ---------------------------------------------------------------------------
// Fused fp32->fp16 prep (unchanged)
// ---------------------------------------------------------------------------
__global__ __launch_bounds__(256)
void prep_h(const float4* __restrict__ x,  const float4* __restrict__ wq,
            const float4* __restrict__ wk, const float4* __restrict__ wv,
            uint2* __restrict__ xh, uint2* __restrict__ wh, int n4x, int n4w)
{
    int i = blockIdx.x * 256 + threadIdx.x;
    const float4* src;
    uint2* dst;
    int off;
    if (i < n4x) { src = x; dst = xh; off = i; }
    else {
        int j = i - n4x;
        int z = j / n4w;
        off = j - z * n4w;
        src = (z == 0) ? wq : (z == 1) ? wk : wv;
        dst = wh + (size_t)z * n4w;
    }
    float4 v = src[off];
    dst[off] = make_uint2(pack_h2(v.x, v.y), pack_h2(v.z, v.w));
}

// ---------------------------------------------------------------------------
// fp16 mma GEMM, tiles 128(M) x 256(N), K-chunk 64, 3-stage, 256 threads.
// Warp tile 64x64 (8 warps: 2m x 4n). Halves L2 traffic for X vs 128x128.
// z=0 -> qth fp16 [M,D], z=1 -> kth fp16 [M,D], z=2 -> g_vh fp16 [B,N,H,T]
// ---------------------------------------------------------------------------
#define G_STG   55296            // A 128x144 (18432) + B 256x144 (36864)
#define GSMEM   (3*G_STG)        // 165888

__global__ __launch_bounds__(256, 1)
void gemm_mma_kernel(const __half* __restrict__ X, const __half* __restrict__ Wall,
                     __half* __restrict__ qth, __half* __restrict__ kth,
                     __half* __restrict__ vh)
{
    extern __shared__ char smem[];
    const uint32_t sb = smem_u32(smem);
    const int t   = threadIdx.x;
    const int w   = t >> 5;
    const int lid = t & 31;
    const int wm  = w >> 2;           // 0..1  (64 M-rows each)
    const int wn  = w & 3;            // 0..3  (64 N-cols each)
    const int lr  = lid >> 2;
    const int lc  = lid & 3;
    const int n0  = blockIdx.x * 256;
    const int m0  = blockIdx.y * 128;
    const int z   = blockIdx.z;
    const __half* W = Wall + (size_t)z * D_ * D_;

    const int l7  = lid & 7;
    const int lm1 = (lid >> 3) & 1;
    const int lm2 = lid >> 4;

    float acc[4][8][4];
#pragma unroll
    for (int i = 0; i < 4; i++)
#pragma unroll
        for (int j = 0; j < 8; j++)
#pragma unroll
            for (int e = 0; e < 4; e++) acc[i][j][e] = 0.f;

    auto load_stage = [&](int stg, int kt) {
        const int k0 = kt * 64;
        uint32_t ab = sb + stg * G_STG;
        uint32_t bb = ab + 18432;
#pragma unroll
        for (int i = 0; i < 4; i++) {          // A: 128 rows x 8 x 16B
            int id  = t + i * 256;             // 0..1023
            int row = id >> 3;
            int c   = id & 7;
            cp16(ab + row * 144 + c * 16, X + (size_t)(m0 + row) * D_ + k0 + c * 8);
        }
#pragma unroll
        for (int i = 0; i < 8; i++) {          // B: 256 rows x 8 x 16B
            int id  = t + i * 256;             // 0..2047
            int row = id >> 3;
            int c   = id & 7;
            cp16(bb + row * 144 + c * 16, W + (size_t)(n0 + row) * D_ + k0 + c * 8);
        }
        cp_commit();
    };

    const int NK = D_ / 64;
    load_stage(0, 0);
    load_stage(1, 1);

#pragma unroll 1
    for (int kt = 0; kt < NK; kt++) {
        if (kt == NK - 1) cp_wait0(); else cp_wait1();
        __syncthreads();
        if (kt + 2 < NK) load_stage((kt + 2) % 3, kt + 2);

        const uint32_t As = sb + (kt % 3) * G_STG;
        const uint32_t Bs = As + 18432;
#pragma unroll
        for (int ks = 0; ks < 4; ks++) {
            uint32_t a[4][4];
#pragma unroll
            for (int mt = 0; mt < 4; mt++) {
                int row = wm * 64 + mt * 16 + l7 + lm1 * 8;
                int kh  = ks * 16 + lm2 * 8;
                ldm_x4(a[mt], As + row * 144 + kh * 2);
            }
#pragma unroll
            for (int ntp = 0; ntp < 4; ntp++) {
                uint32_t b[4];
                int nr = wn * 64 + ntp * 16 + l7 + lm2 * 8;
                int kh = ks * 16 + lm1 * 8;
                ldm_x4(b, Bs + nr * 144 + kh * 2);
#pragma unroll
                for (int mt = 0; mt < 4; mt++) {
                    mma_f16(acc[mt][2*ntp],   a[mt], b);
                    mma_f16(acc[mt][2*ntp+1], a[mt], b + 2);
                }
            }
        }
    }

    // ---- epilogue ----
#pragma unroll
    for (int mt = 0; mt < 4; mt++) {
#pragma unroll
        for (int j = 0; j < 8; j++) {
            int row  = wm * 64 + mt * 16 + lr;
            int m    = m0 + row;
            int colg = n0 + wn * 64 + j * 8 + 2 * lc;
            uint32_t p0 = pack_h2(acc[mt][j][0], acc[mt][j][1]);
            uint32_t p1 = pack_h2(acc[mt][j][2], acc[mt][j][3]);
            if (z == 0) {
                *(uint32_t*)(qth + (size_t)m * D_ + colg)       = p0;
                *(uint32_t*)(qth + (size_t)(m + 8) * D_ + colg) = p1;
            } else if (z == 1) {
                *(uint32_t*)(kth + (size_t)m * D_ + colg)       = p0;
                *(uint32_t*)(kth + (size_t)(m + 8) * D_ + colg) = p1;
            } else {
                int b    = m >> 11;
                int tp   = m & (T_ - 1);
                int head = colg >> 7;
                int h    = colg & (H_ - 1);
                __half* vb = vh + ((size_t)(b * NH_ + head) * H_ + h) * T_ + tp;
                vb[0]      = __float2half(acc[mt][j][0]);
                vb[T_]     = __float2half(acc[mt][j][1]);
                vb[8]      = __float2half(acc[mt][j][2]);
                vb[T_ + 8] = __float2half(acc[mt][j][3]);
            }
        }
    }
}

// ---------------------------------------------------------------------------
// RoPE + transpose. Q output pre-scaled by scale*log2e (log2-domain scores).
// ---------------------------------------------------------------------------
#define SC2 (0.08838834764831845f * 1.4426950408889634f)

__global__ __launch_bounds__(256)
void rope_kernel(const __half* __restrict__ q, const __half* __restrict__ k,
                 const float* __restrict__ cosb, const float* __restrict__ sinb,
                 __half* __restrict__ qo, __half* __restrict__ ko)
{
    int i = blockIdx.x * 256 + threadIdx.x;
    int dp   = (i & 511) * 2;
    int row  = i >> 9;
    int tpos = row & (T_ - 1);
    int b    = row >> 11;

    float2 c2 = *(const float2*)(cosb + (size_t)tpos * D_ + dp);
    float2 s2 = *(const float2*)(sinb + (size_t)tpos * D_ + dp);
    size_t base = (size_t)row * D_;

    __half2 qv = *(const __half2*)(q + base + dp);
    __half2 kv = *(const __half2*)(k + base + dp);
    float q0 = __half2float(qv.x), q1 = __half2float(qv.y);
    float k0 = __half2float(kv.x), k1 = __half2float(kv.y);

    float qr0, qr1, kr0, kr1;
    if (dp < D_/2) {
        const __half2* qp = (const __half2*)(q + base + 2 * dp);
        const __half2* kp = (const __half2*)(k + base + 2 * dp);
        __half2 a = qp[0], bq = qp[1];
        __half2 c = kp[0], dk = kp[1];
        qr0 = -__half2float(a.y);  qr1 = -__half2float(bq.y);
        kr0 = -__half2float(c.y);  kr1 = -__half2float(dk.y);
    } else {
        int j = dp - D_/2;
        const __half2* qp = (const __half2*)(q + base + 2 * j);
        const __half2* kp = (const __half2*)(k + base + 2 * j);
        __half2 a = qp[0], bq = qp[1];
        __half2 c = kp[0], dk = kp[1];
        qr0 = __half2float(a.x);   qr1 = __half2float(bq.x);
        kr0 = __half2float(c.x);   kr1 = __half2float(dk.x);
    }

    int head = dp >> 7;
    int h    = dp & (H_ - 1);
    size_t oidx = ((((size_t)b*NH_ + head)*T_) + tpos)*H_ + h;
    *(__half2*)(qo + oidx) = __floats2half2_rn((q0 * c2.x + qr0 * s2.x) * SC2,
                                               (q1 * c2.y + qr1 * s2.y) * SC2);
    *(__half2*)(ko + oidx) = __floats2half2_rn(k0 * c2.x + kr0 * s2.x,
                                               k1 * c2.y + kr1 * s2.y);
}

// ---------------------------------------------------------------------------
// fp16 FA (unchanged from round 13): Br=64, Bc=64, 128 thr, 2 CTAs/SM,
// static-max softmax, Q frags hoisted, row sums via ones-MMA.
// ---------------------------------------------------------------------------
#define AQ_BYTES    17408
#define AK_BYTES    17408
#define AV_BYTES    18432
#define ASTG_BYTES  (AK_BYTES + AV_BYTES)
#define AKS_OFF(s)  (AQ_BYTES + (s)*ASTG_BYTES)
#define AVS_OFF(s)  (AKS_OFF(s) + AK_BYTES)
#define ATTN_SMEM   (AQ_BYTES + 2*ASTG_BYTES)       // 89088

__global__ __launch_bounds__(128, 2)
void attn_kernel(const __half* __restrict__ Q, const __half* __restrict__ K,
                 const __half* __restrict__ V, float* __restrict__ out)
{
    extern __shared__ char smem[];
    const uint32_t sb = smem_u32(smem);
    const int t   = threadIdx.x;
    const int w   = t >> 5;
    const int lid = t & 31;
    const int lr  = lid >> 2;
    const int lc  = lid & 3;
    const int l7  = lid & 7;
    const int lm1 = (lid >> 3) & 1;
    const int lm2 = lid >> 4;
    const int qi  = (gridDim.x - 1) - blockIdx.x;
    const int bn  = blockIdx.y;
    const int q0  = qi * 64;

    const __half* Qg = Q + ((size_t)bn * T_ + q0) * H_;
    const __half* Kg = K + (size_t)bn * T_ * H_;
    const __half* Vg = V + (size_t)bn * H_ * T_;

    auto load_kv = [&](int kt, int stg) {
        const int k0 = kt * 64;
        const uint32_t kb = sb + AKS_OFF(stg);
        const uint32_t vb = sb + AVS_OFF(stg);
#pragma unroll
        for (int i = 0; i < 8; i++) {
            int id  = t + i * 128;
            int row = id >> 4;
            int c   = id & 15;
            cp16(kb + row * 272 + c * 16, Kg + (size_t)(k0 + row) * H_ + c * 8);
        }
#pragma unroll
        for (int i = 0; i < 8; i++) {
            int id  = t + i * 128;
            int row = id >> 3;
            int c   = id & 7;
            cp16(vb + row * 144 + c * 16, Vg + (size_t)row * T_ + k0 + c * 8);
        }
        cp_commit();
    };

#pragma unroll
    for (int i = 0; i < 8; i++) {
        int id  = t + i * 128;
        int row = id >> 4;
        int c   = id & 15;
        cp16(sb + row * 272 + c * 16, Qg + row * H_ + c * 8);
    }
    const int nkt = qi + 1;
    load_kv(0, 0);
    if (nkt > 1) load_kv(1, 1);

    if (nkt > 1) cp_wait1(); else cp_wait0();
    __syncthreads();
    uint32_t qa[8][4];
#pragma unroll
    for (int ks = 0; ks < 8; ks++)
        ldm_x4(qa[ks], sb + (w * 16 + l7 + lm1 * 8) * 272 + (ks * 16 + lm2 * 8) * 2);

    float o[16][4];
#pragma unroll
    for (int i = 0; i < 16; i++)
#pragma unroll
        for (int e = 0; e < 4; e++) o[i][e] = 0.f;
    float ls[4] = {0.f, 0.f, 0.f, 0.f};
    const uint32_t ones2[2] = {0x3C003C00u, 0x3C003C00u};

#pragma unroll 1
    for (int kt = 0; kt < nkt; kt++) {
        if (kt > 0) {
            if (kt >= nkt - 1) cp_wait0(); else cp_wait1();
            __syncthreads();
        }

        const int stg = kt & 1;
        const uint32_t Ksb = sb + AKS_OFF(stg);
        const uint32_t Vsb = sb + AVS_OFF(stg);

        float s[8][4];
#pragma unroll
        for (int nt = 0; nt < 8; nt++)
#pragma unroll
            for (int e = 0; e < 4; e++) s[nt][e] = 0.f;

#pragma unroll
        for (int ks = 0; ks < 8; ks++) {
#pragma unroll
            for (int ntp = 0; ntp < 4; ntp++) {
                uint32_t b[4];
                ldm_x4(b, Ksb + (ntp * 16 + l7 + lm2 * 8) * 272 + (ks * 16 + lm1 * 8) * 2);
                mma_f16(s[2*ntp],   qa[ks], b);
                mma_f16(s[2*ntp+1], qa[ks], b + 2);
            }
        }

        if (kt == qi) {
            const int row0 = w * 16 + lr;
#pragma unroll
            for (int nt = 0; nt < 8; nt++) {
                int c0 = nt * 8 + 2 * lc;
                if (c0     > row0)     s[nt][0] = -1e30f;
                if (c0 + 1 > row0)     s[nt][1] = -1e30f;
                if (c0     > row0 + 8) s[nt][2] = -1e30f;
                if (c0 + 1 > row0 + 8) s[nt][3] = -1e30f;
            }
        }

#pragma unroll
        for (int nt = 0; nt < 8; nt++) {
            s[nt][0] = ex2(s[nt][0]);
            s[nt][1] = ex2(s[nt][1]);
            s[nt][2] = ex2(s[nt][2]);
            s[nt][3] = ex2(s[nt][3]);
        }

#pragma unroll
        for (int kc = 0; kc < 4; kc++) {
            uint32_t pa[4];
            pa[0] = pack_h2(s[2*kc][0],   s[2*kc][1]);
            pa[1] = pack_h2(s[2*kc][2],   s[2*kc][3]);
            pa[2] = pack_h2(s[2*kc+1][0], s[2*kc+1][1]);
            pa[3] = pack_h2(s[2*kc+1][2], s[2*kc+1][3]);
            mma_f16(ls, pa, ones2);
            const int th = kc * 16 + lm1 * 8;
#pragma unroll
            for (int ntp = 0; ntp < 8; ntp++) {
                uint32_t b[4];
                ldm_x4(b, Vsb + (ntp * 16 + l7 + lm2 * 8) * 144 + th * 2);
                mma_f16(o[2*ntp],   pa, b);
                mma_f16(o[2*ntp+1], pa, b + 2);
            }
        }

        __syncthreads();
        if (kt + 2 < nkt) load_kv(kt + 2, stg);
    }

    const float inv0 = 1.f / ls[0], inv1 = 1.f / ls[2];
    const int b    = bn >> 3;
    const int head = bn & 7;
    const int trow = q0 + w * 16 + lr;
    float* base0 = out + ((size_t)b * T_ + trow) * D_ + head * H_ + 2 * lc;
    float* base1 = base0 + 8 * (size_t)D_;
#pragma unroll
    for (int nt2 = 0; nt2 < 16; nt2++) {
        *(float2*)(base0 + nt2 * 8) = make_float2(o[nt2][0] * inv0, o[nt2][1] * inv0);
        *(float2*)(base1 + nt2 * 8) = make_float2(o[nt2][2] * inv1, o[nt2][3] * inv1);
    }
}

// ---------------------------------------------------------------------------
extern "C" void kernel_launch(void* const* d_in, const int* in_sizes, int n_in,
                              void* d_out, int out_size)
{
    const float* x    = (const float*)d_in[0];
    const float* wq   = (const float*)d_in[1];
    const float* wk   = (const float*)d_in[2];
    const float* wv   = (const float*)d_in[3];
    const float* cosb = (const float*)d_in[4];
    const float* sinb = (const float*)d_in[5];
    float* out = (float*)d_out;

    __half *qth, *kth, *qh, *kh, *vh, *xh, *wh;
    cudaGetSymbolAddress((void**)&qth, g_qth);
    cudaGetSymbolAddress((void**)&kth, g_kth);
    cudaGetSymbolAddress((void**)&qh,  g_qh);
    cudaGetSymbolAddress((void**)&kh,  g_kh);
    cudaGetSymbolAddress((void**)&vh,  g_vh);
    cudaGetSymbolAddress((void**)&xh,  g_xh);
    cudaGetSymbolAddress((void**)&wh,  g_wh);

    const int n4x = (M_ * D_) / 4;
    const int n4w = (D_ * D_) / 4;
    const int ntot = n4x + 3 * n4w;
    prep_h<<<ntot / 256, 256>>>((const float4*)x, (const float4*)wq,
                                (const float4*)wk, (const float4*)wv,
                                (uint2*)xh, (uint2*)wh, n4x, n4w);

    cudaFuncSetAttribute((const void*)gemm_mma_kernel,
                         cudaFuncAttributeMaxDynamicSharedMemorySize, GSMEM);
    gemm_mma_kernel<<<dim3(D_/256, M_/128, 3), 256, GSMEM>>>(xh, wh, qth, kth, vh);

    rope_kernel<<<(M_*D_/2) / 256, 256>>>(qth, kth, cosb, sinb, qh, kh);

    cudaFuncSetAttribute((const void*)attn_kernel,
                         cudaFuncAttributeMaxDynamicSharedMemorySize, ATTN_SMEM);
    attn_kernel<<<dim3(T_/64, B_*NH_), 128, ATTN_SMEM>>>(qh, kh, vh, out);
}

// round 15
// speedup vs baseline: 1.6481x; 1.6481x over previous
#include <cuda_runtime.h>
#include <cuda_fp16.h>
#include <math.h>
#include <stdint.h>

#define B_   4
#define T_   2048
#define D_   1024
#define NH_  8
#define H_   128
#define M_   (B_*T_)

// ---------------- scratch ----------------------------------------------------
__device__ __half g_qth[(size_t)M_*D_];    // q pre-rope fp16 [M,D]
__device__ __half g_kth[(size_t)M_*D_];    // k pre-rope fp16 [M,D]
__device__ __half g_qh[(size_t)M_*D_];     // [B,N,T,H] fp16 (pre-scaled by SC2)
__device__ __half g_kh[(size_t)M_*D_];     // [B,N,T,H] fp16
__device__ __half g_vh[(size_t)M_*D_];     // [B,N,H,T] fp16 (h-major)
__device__ __half g_xh[(size_t)M_*D_];     // x fp16
__device__ __half g_wh[(size_t)3*D_*D_];   // wq|wk|wv fp16

// ---------------- helpers ----------------------------------------------------
static __device__ __forceinline__ uint32_t smem_u32(const void* p) {
    uint32_t a;
    asm("{ .reg .u64 t; cvta.to.shared.u64 t, %1; cvt.u32.u64 %0, t; }"
        : "=r"(a) : "l"(p));
    return a;
}
static __device__ __forceinline__ void cp16(uint32_t dst, const void* src) {
    asm volatile("cp.async.cg.shared.global [%0], [%1], 16;" :: "r"(dst), "l"(src));
}
static __device__ __forceinline__ void cp_commit() {
    asm volatile("cp.async.commit_group;");
}
static __device__ __forceinline__ void cp_wait0() {
    asm volatile("cp.async.wait_group 0;" ::: "memory");
}
static __device__ __forceinline__ void cp_wait1() {
    asm volatile("cp.async.wait_group 1;" ::: "memory");
}
static __device__ __forceinline__ void mma_f16(float* d, const uint32_t* a,
                                               const uint32_t* b) {
    asm volatile(
        "mma.sync.aligned.m16n8k16.row.col.f32.f16.f16.f32 "
        "{%0,%1,%2,%3}, {%4,%5,%6,%7}, {%8,%9}, {%0,%1,%2,%3};"
        : "+f"(d[0]), "+f"(d[1]), "+f"(d[2]), "+f"(d[3])
        : "r"(a[0]), "r"(a[1]), "r"(a[2]), "r"(a[3]), "r"(b[0]), "r"(b[1]));
}
static __device__ __forceinline__ void ldm_x4(uint32_t* r, uint32_t addr) {
    asm volatile("ldmatrix.sync.aligned.m8n8.x4.shared.b16 {%0,%1,%2,%3}, [%4];"
        : "=r"(r[0]), "=r"(r[1]), "=r"(r[2]), "=r"(r[3]) : "r"(addr));
}
static __device__ __forceinline__ uint32_t pack_h2(float x, float y) {
    __half2 h = __floats2half2_rn(x, y);
    uint32_t u;
    memcpy(&u, &h, 4);
    return u;
}
static __device__ __forceinline__ float ex2(float x) {
    float r;
    asm("ex2.approx.f32 %0, %1;" : "=f"(r) : "f"(x));
    return r;
}

// ---------------------------------------------------------------------------
// Fused fp32->fp16 prep (unchanged)
// ---------------------------------------------------------------------------
__global__ __launch_bounds__(256)
void prep_h(const float4* __restrict__ x,  const float4* __restrict__ wq,
            const float4* __restrict__ wk, const float4* __restrict__ wv,
            uint2* __restrict__ xh, uint2* __restrict__ wh, int n4x, int n4w)
{
    int i = blockIdx.x * 256 + threadIdx.x;
    const float4* src;
    uint2* dst;
    int off;
    if (i < n4x) { src = x; dst = xh; off = i; }
    else {
        int j = i - n4x;
        int z = j / n4w;
        off = j - z * n4w;
        src = (z == 0) ? wq : (z == 1) ? wk : wv;
        dst = wh + (size_t)z * n4w;
    }
    float4 v = src[off];
    dst[off] = make_uint2(pack_h2(v.x, v.y), pack_h2(v.z, v.w));
}

// ---------------------------------------------------------------------------
// fp16 mma GEMM, 128x128 tiles, K-chunk 64, 3-stage, 256 thr, 2 CTAs/SM.
// zbase + blockIdx.z selects weight: 0 -> qth, 1 -> kth, 2 -> g_vh [B,N,H,T]
// ---------------------------------------------------------------------------
#define GSTAGE 36864
#define GSMEM  (3*GSTAGE)

__global__ __launch_bounds__(256, 2)
void gemm_mma_kernel(const __half* __restrict__ X, const __half* __restrict__ Wall,
                     __half* __restrict__ qth, __half* __restrict__ kth,
                     __half* __restrict__ vh, int zbase)
{
    extern __shared__ char smem[];
    const uint32_t sb = smem_u32(smem);
    const int t   = threadIdx.x;
    const int w   = t >> 5;
    const int lid = t & 31;
    const int wm  = w >> 2;
    const int wn  = w & 3;
    const int lr  = lid >> 2;
    const int lc  = lid & 3;
    const int n0  = blockIdx.x * 128;
    const int m0  = blockIdx.y * 128;
    const int z   = blockIdx.z + zbase;
    const __half* W = Wall + (size_t)z * D_ * D_;

    const int l7  = lid & 7;
    const int lm1 = (lid >> 3) & 1;
    const int lm2 = lid >> 4;

    float acc[4][4][4];
#pragma unroll
    for (int i = 0; i < 4; i++)
#pragma unroll
        for (int j = 0; j < 4; j++)
#pragma unroll
            for (int e = 0; e < 4; e++) acc[i][j][e] = 0.f;

    auto load_stage = [&](int stg, int kt) {
        const int k0 = kt * 64;
        uint32_t ab = sb + stg * GSTAGE;
        uint32_t bb = ab + 18432;
#pragma unroll
        for (int i = 0; i < 4; i++) {
            int id  = t + i * 256;
            int row = id >> 3;
            int c   = id & 7;
            cp16(ab + row * 144 + c * 16, X + (size_t)(m0 + row) * D_ + k0 + c * 8);
            cp16(bb + row * 144 + c * 16, W + (size_t)(n0 + row) * D_ + k0 + c * 8);
        }
        cp_commit();
    };

    const int NK = D_ / 64;
    load_stage(0, 0);
    load_stage(1, 1);

#pragma unroll 1
    for (int kt = 0; kt < NK; kt++) {
        if (kt == NK - 1) cp_wait0(); else cp_wait1();
        __syncthreads();
        if (kt + 2 < NK) load_stage((kt + 2) % 3, kt + 2);

        const uint32_t As = sb + (kt % 3) * GSTAGE;
        const uint32_t Bs = As + 18432;
#pragma unroll
        for (int ks = 0; ks < 4; ks++) {
            uint32_t a[4][4];
#pragma unroll
            for (int mt = 0; mt < 4; mt++) {
                int row = wm * 64 + mt * 16 + l7 + lm1 * 8;
                int kh  = ks * 16 + lm2 * 8;
                ldm_x4(a[mt], As + row * 144 + kh * 2);
            }
#pragma unroll
            for (int ntp = 0; ntp < 2; ntp++) {
                uint32_t b[4];
                int nr = wn * 32 + ntp * 16 + l7 + lm2 * 8;
                int kh = ks * 16 + lm1 * 8;
                ldm_x4(b, Bs + nr * 144 + kh * 2);
#pragma unroll
                for (int mt = 0; mt < 4; mt++) {
                    mma_f16(acc[mt][2*ntp],   a[mt], b);
                    mma_f16(acc[mt][2*ntp+1], a[mt], b + 2);
                }
            }
        }
    }

#pragma unroll
    for (int mt = 0; mt < 4; mt++) {
#pragma unroll
        for (int nt = 0; nt < 4; nt++) {
            int row = wm * 64 + mt * 16 + lr;
            int col = wn * 32 + nt * 8 + 2 * lc;
            int m   = m0 + row;
            uint32_t p0 = pack_h2(acc[mt][nt][0], acc[mt][nt][1]);
            uint32_t p1 = pack_h2(acc[mt][nt][2], acc[mt][nt][3]);
            if (z == 0) {
                *(uint32_t*)(qth + (size_t)m * D_ + n0 + col)       = p0;
                *(uint32_t*)(qth + (size_t)(m + 8) * D_ + n0 + col) = p1;
            } else if (z == 1) {
                *(uint32_t*)(kth + (size_t)m * D_ + n0 + col)       = p0;
                *(uint32_t*)(kth + (size_t)(m + 8) * D_ + n0 + col) = p1;
            } else {
                int b    = m >> 11;
                int tp   = m & (T_ - 1);
                int head = blockIdx.x;
                __half* vb = vh + ((size_t)(b * NH_ + head) * H_ + col) * T_ + tp;
                vb[0]      = __float2half(acc[mt][nt][0]);
                vb[T_]     = __float2half(acc[mt][nt][1]);
                vb[8]      = __float2half(acc[mt][nt][2]);
                vb[T_ + 8] = __float2half(acc[mt][nt][3]);
            }
        }
    }
}

// ---------------------------------------------------------------------------
// RoPE + transpose. Q output pre-scaled by scale*log2e (log2-domain scores).
// ---------------------------------------------------------------------------
#define SC2 (0.08838834764831845f * 1.4426950408889634f)

__global__ __launch_bounds__(256)
void rope_kernel(const __half* __restrict__ q, const __half* __restrict__ k,
                 const float* __restrict__ cosb, const float* __restrict__ sinb,
                 __half* __restrict__ qo, __half* __restrict__ ko)
{
    int i = blockIdx.x * 256 + threadIdx.x;
    int dp   = (i & 511) * 2;
    int row  = i >> 9;
    int tpos = row & (T_ - 1);
    int b    = row >> 11;

    float2 c2 = *(const float2*)(cosb + (size_t)tpos * D_ + dp);
    float2 s2 = *(const float2*)(sinb + (size_t)tpos * D_ + dp);
    size_t base = (size_t)row * D_;

    __half2 qv = *(const __half2*)(q + base + dp);
    __half2 kv = *(const __half2*)(k + base + dp);
    float q0 = __half2float(qv.x), q1 = __half2float(qv.y);
    float k0 = __half2float(kv.x), k1 = __half2float(kv.y);

    float qr0, qr1, kr0, kr1;
    if (dp < D_/2) {
        const __half2* qp = (const __half2*)(q + base + 2 * dp);
        const __half2* kp = (const __half2*)(k + base + 2 * dp);
        __half2 a = qp[0], bq = qp[1];
        __half2 c = kp[0], dk = kp[1];
        qr0 = -__half2float(a.y);  qr1 = -__half2float(bq.y);
        kr0 = -__half2float(c.y);  kr1 = -__half2float(dk.y);
    } else {
        int j = dp - D_/2;
        const __half2* qp = (const __half2*)(q + base + 2 * j);
        const __half2* kp = (const __half2*)(k + base + 2 * j);
        __half2 a = qp[0], bq = qp[1];
        __half2 c = kp[0], dk = kp[1];
        qr0 = __half2float(a.x);   qr1 = __half2float(bq.x);
        kr0 = __half2float(c.x);   kr1 = __half2float(dk.x);
    }

    int head = dp >> 7;
    int h    = dp & (H_ - 1);
    size_t oidx = ((((size_t)b*NH_ + head)*T_) + tpos)*H_ + h;
    *(__half2*)(qo + oidx) = __floats2half2_rn((q0 * c2.x + qr0 * s2.x) * SC2,
                                               (q1 * c2.y + qr1 * s2.y) * SC2);
    *(__half2*)(ko + oidx) = __floats2half2_rn(k0 * c2.x + kr0 * s2.x,
                                               k1 * c2.y + kr1 * s2.y);
}

// ---------------------------------------------------------------------------
// fp16 FA (unchanged from round 13): Br=64, Bc=64, 128 thr, 2 CTAs/SM,
// static-max softmax, Q frags hoisted, row sums via ones-MMA.
// ---------------------------------------------------------------------------
#define AQ_BYTES    17408
#define AK_BYTES    17408
#define AV_BYTES    18432
#define ASTG_BYTES  (AK_BYTES + AV_BYTES)
#define AKS_OFF(s)  (AQ_BYTES + (s)*ASTG_BYTES)
#define AVS_OFF(s)  (AKS_OFF(s) + AK_BYTES)
#define ATTN_SMEM   (AQ_BYTES + 2*ASTG_BYTES)       // 89088

__global__ __launch_bounds__(128, 2)
void attn_kernel(const __half* __restrict__ Q, const __half* __restrict__ K,
                 const __half* __restrict__ V, float* __restrict__ out)
{
    extern __shared__ char smem[];
    const uint32_t sb = smem_u32(smem);
    const int t   = threadIdx.x;
    const int w   = t >> 5;
    const int lid = t & 31;
    const int lr  = lid >> 2;
    const int lc  = lid & 3;
    const int l7  = lid & 7;
    const int lm1 = (lid >> 3) & 1;
    const int lm2 = lid >> 4;
    const int qi  = (gridDim.x - 1) - blockIdx.x;
    const int bn  = blockIdx.y;
    const int q0  = qi * 64;

    const __half* Qg = Q + ((size_t)bn * T_ + q0) * H_;
    const __half* Kg = K + (size_t)bn * T_ * H_;
    const __half* Vg = V + (size_t)bn * H_ * T_;

    auto load_kv = [&](int kt, int stg) {
        const int k0 = kt * 64;
        const uint32_t kb = sb + AKS_OFF(stg);
        const uint32_t vb = sb + AVS_OFF(stg);
#pragma unroll
        for (int i = 0; i < 8; i++) {
            int id  = t + i * 128;
            int row = id >> 4;
            int c   = id & 15;
            cp16(kb + row * 272 + c * 16, Kg + (size_t)(k0 + row) * H_ + c * 8);
        }
#pragma unroll
        for (int i = 0; i < 8; i++) {
            int id  = t + i * 128;
            int row = id >> 3;
            int c   = id & 7;
            cp16(vb + row * 144 + c * 16, Vg + (size_t)row * T_ + k0 + c * 8);
        }
        cp_commit();
    };

#pragma unroll
    for (int i = 0; i < 8; i++) {
        int id  = t + i * 128;
        int row = id >> 4;
        int c   = id & 15;
        cp16(sb + row * 272 + c * 16, Qg + row * H_ + c * 8);
    }
    const int nkt = qi + 1;
    load_kv(0, 0);
    if (nkt > 1) load_kv(1, 1);

    if (nkt > 1) cp_wait1(); else cp_wait0();
    __syncthreads();
    uint32_t qa[8][4];
#pragma unroll
    for (int ks = 0; ks < 8; ks++)
        ldm_x4(qa[ks], sb + (w * 16 + l7 + lm1 * 8) * 272 + (ks * 16 + lm2 * 8) * 2);

    float o[16][4];
#pragma unroll
    for (int i = 0; i < 16; i++)
#pragma unroll
        for (int e = 0; e < 4; e++) o[i][e] = 0.f;
    float ls[4] = {0.f, 0.f, 0.f, 0.f};
    const uint32_t ones2[2] = {0x3C003C00u, 0x3C003C00u};

#pragma unroll 1
    for (int kt = 0; kt < nkt; kt++) {
        if (kt > 0) {
            if (kt >= nkt - 1) cp_wait0(); else cp_wait1();
            __syncthreads();
        }

        const int stg = kt & 1;
        const uint32_t Ksb = sb + AKS_OFF(stg);
        const uint32_t Vsb = sb + AVS_OFF(stg);

        float s[8][4];
#pragma unroll
        for (int nt = 0; nt < 8; nt++)
#pragma unroll
            for (int e = 0; e < 4; e++) s[nt][e] = 0.f;

#pragma unroll
        for (int ks = 0; ks < 8; ks++) {
#pragma unroll
            for (int ntp = 0; ntp < 4; ntp++) {
                uint32_t b[4];
                ldm_x4(b, Ksb + (ntp * 16 + l7 + lm2 * 8) * 272 + (ks * 16 + lm1 * 8) * 2);
                mma_f16(s[2*ntp],   qa[ks], b);
                mma_f16(s[2*ntp+1], qa[ks], b + 2);
            }
        }

        if (kt == qi) {
            const int row0 = w * 16 + lr;
#pragma unroll
            for (int nt = 0; nt < 8; nt++) {
                int c0 = nt * 8 + 2 * lc;
                if (c0     > row0)     s[nt][0] = -1e30f;
                if (c0 + 1 > row0)     s[nt][1] = -1e30f;
                if (c0     > row0 + 8) s[nt][2] = -1e30f;
                if (c0 + 1 > row0 + 8) s[nt][3] = -1e30f;
            }
        }

#pragma unroll
        for (int nt = 0; nt < 8; nt++) {
            s[nt][0] = ex2(s[nt][0]);
            s[nt][1] = ex2(s[nt][1]);
            s[nt][2] = ex2(s[nt][2]);
            s[nt][3] = ex2(s[nt][3]);
        }

#pragma unroll
        for (int kc = 0; kc < 4; kc++) {
            uint32_t pa[4];
            pa[0] = pack_h2(s[2*kc][0],   s[2*kc][1]);
            pa[1] = pack_h2(s[2*kc][2],   s[2*kc][3]);
            pa[2] = pack_h2(s[2*kc+1][0], s[2*kc+1][1]);
            pa[3] = pack_h2(s[2*kc+1][2], s[2*kc+1][3]);
            mma_f16(ls, pa, ones2);
            const int th = kc * 16 + lm1 * 8;
#pragma unroll
            for (int ntp = 0; ntp < 8; ntp++) {
                uint32_t b[4];
                ldm_x4(b, Vsb + (ntp * 16 + l7 + lm2 * 8) * 144 + th * 2);
                mma_f16(o[2*ntp],   pa, b);
                mma_f16(o[2*ntp+1], pa, b + 2);
            }
        }

        __syncthreads();
        if (kt + 2 < nkt) load_kv(kt + 2, stg);
    }

    const float inv0 = 1.f / ls[0], inv1 = 1.f / ls[2];
    const int b    = bn >> 3;
    const int head = bn & 7;
    const int trow = q0 + w * 16 + lr;
    float* base0 = out + ((size_t)b * T_ + trow) * D_ + head * H_ + 2 * lc;
    float* base1 = base0 + 8 * (size_t)D_;
#pragma unroll
    for (int nt2 = 0; nt2 < 16; nt2++) {
        *(float2*)(base0 + nt2 * 8) = make_float2(o[nt2][0] * inv0, o[nt2][1] * inv0);
        *(float2*)(base1 + nt2 * 8) = make_float2(o[nt2][2] * inv1, o[nt2][3] * inv1);
    }
}

// ---------------------------------------------------------------------------
extern "C" void kernel_launch(void* const* d_in, const int* in_sizes, int n_in,
                              void* d_out, int out_size)
{
    const float* x    = (const float*)d_in[0];
    const float* wq   = (const float*)d_in[1];
    const float* wk   = (const float*)d_in[2];
    const float* wv   = (const float*)d_in[3];
    const float* cosb = (const float*)d_in[4];
    const float* sinb = (const float*)d_in[5];
    float* out = (float*)d_out;

    __half *qth, *kth, *qh, *kh, *vh, *xh, *wh;
    cudaGetSymbolAddress((void**)&qth, g_qth);
    cudaGetSymbolAddress((void**)&kth, g_kth);
    cudaGetSymbolAddress((void**)&qh,  g_qh);
    cudaGetSymbolAddress((void**)&kh,  g_kh);
    cudaGetSymbolAddress((void**)&vh,  g_vh);
    cudaGetSymbolAddress((void**)&xh,  g_xh);
    cudaGetSymbolAddress((void**)&wh,  g_wh);

    // one-time host-side handles (no device memory; identical work every call)
    static cudaStream_t s2 = nullptr;
    static cudaEvent_t evP = nullptr, evV = nullptr;
    if (s2 == nullptr) {
        cudaStreamCreateWithFlags(&s2, cudaStreamNonBlocking);
        cudaEventCreateWithFlags(&evP, cudaEventDisableTiming);
        cudaEventCreateWithFlags(&evV, cudaEventDisableTiming);
    }

    const int n4x = (M_ * D_) / 4;
    const int n4w = (D_ * D_) / 4;
    const int ntot = n4x + 3 * n4w;
    prep_h<<<ntot / 256, 256>>>((const float4*)x, (const float4*)wq,
                                (const float4*)wk, (const float4*)wv,
                                (uint2*)xh, (uint2*)wh, n4x, n4w);
    cudaEventRecord(evP, 0);

    cudaFuncSetAttribute((const void*)gemm_mma_kernel,
                         cudaFuncAttributeMaxDynamicSharedMemorySize, GSMEM);

    // fork: V-GEMM on s2 runs concurrently with QK-GEMM + rope on stream 0
    cudaStreamWaitEvent(s2, evP, 0);
    gemm_mma_kernel<<<dim3(D_/128, M_/128, 1), 256, GSMEM, s2>>>(xh, wh, qth, kth, vh, 2);
    cudaEventRecord(evV, s2);

    gemm_mma_kernel<<<dim3(D_/128, M_/128, 2), 256, GSMEM>>>(xh, wh, qth, kth, vh, 0);
    rope_kernel<<<(M_*D_/2) / 256, 256>>>(qth, kth, cosb, sinb, qh, kh);

    cudaStreamWaitEvent(0, evV, 0);   // join before attention
    cudaFuncSetAttribute((const void*)attn_kernel,
                         cudaFuncAttributeMaxDynamicSharedMemorySize, ATTN_SMEM);
    attn_kernel<<<dim3(T_/64, B_*NH_), 128, ATTN_SMEM>>>(qh, kh, vh, out);
}